// round 13
// baseline (speedup 1.0000x reference)
#include <cuda_runtime.h>
#include <cuda_bf16.h>
#include <math.h>

#define BB   256
#define TT   512
#define HH   128
#define SS   4
#define DTC  0.1f

// device-global scratch (allocation-free)
__device__ float g_xproj[(size_t)BB * TT * HH];   // 64 MB, [b][t][h]
__device__ float g_hT[SS * BB * HH];

// ---- shared layout (float offsets) ----
#define OFF_WI   0            // 128*132 ROW-major [col][k], pad 132
#define OFF_V1   16896        // 32*132
#define OFF_V2   21120        // 128*36
#define OFF_BC   25728
#define OFF_V2B  25856
#define OFF_V1B  25984
#define OFF_GRP  26016
// per-group (256 threads): sh 896 | sx 896 | sp 7168 | sqp 1792 | sqs 224 | sred 32
#define GRP_STRIDE 11008
#define SMEM_FLOATS (OFF_GRP + 2 * GRP_STRIDE)
#define SMEM_BYTES  (SMEM_FLOATS * 4)   // 192128 B

__device__ __forceinline__ float fast_tanh(float x) {
    float ax = fminf(fabsf(x), 12.0f);
    float e  = __expf(2.0f * ax);
    float r  = __fdividef(e - 1.0f, e + 1.0f);
    return copysignf(r, x);
}

// ---------------------------------------------------------------------------
// K1: x_proj = x @ Wp^T + bp
// ---------------------------------------------------------------------------
__global__ __launch_bounds__(128) void xproj_kernel(
    const float* __restrict__ x, const float* __restrict__ Wp,
    const float* __restrict__ bp)
{
    __shared__ float sW[128 * 36];
    __shared__ float sx[32 * 32];
    __shared__ float sb[128];
    const int tid = threadIdx.x;

    for (int idx = tid; idx < 128 * 32; idx += 128) {
        int j = idx >> 5, k = idx & 31;
        sW[j * 36 + k] = Wp[idx];
    }
    sb[tid] = bp[tid];
    const size_t base = (size_t)blockIdx.x * 32;
    for (int idx = tid; idx < 1024; idx += 128)
        sx[idx] = x[base * 32 + idx];
    __syncthreads();

    float acc[32];
    const float b = sb[tid];
    #pragma unroll
    for (int r = 0; r < 32; r++) acc[r] = b;

    #pragma unroll 2
    for (int kk = 0; kk < 32; kk += 4) {
        const float4 w4 = *(const float4*)&sW[tid * 36 + kk];
        #pragma unroll
        for (int r = 0; r < 32; r++) {
            const float4 x4 = *(const float4*)&sx[r * 32 + kk];
            acc[r] = fmaf(x4.x, w4.x, acc[r]);
            acc[r] = fmaf(x4.y, w4.y, acc[r]);
            acc[r] = fmaf(x4.z, w4.z, acc[r]);
            acc[r] = fmaf(x4.w, w4.w, acc[r]);
        }
    }
    #pragma unroll
    for (int r = 0; r < 32; r++)
        g_xproj[(base + r) * HH + tid] = acc[r];
}

// ---------------------------------------------------------------------------
// K2: persistent liquid recurrence.
// 512 threads = 2 independent groups of 256 (8 warps, named barriers).
// GEMM phases: 8-way k-split — warp w handles k in [16w, 16w+16), thread
// (w,l) owns cols 4l..4l+3 with its Wrec slice (64 floats) in registers.
// Owner phases: threads gtid<128, one column each.
// ---------------------------------------------------------------------------
template<int G, int NS>
__device__ __forceinline__ void run_group(
    const float* __restrict__ Wrec, const float* __restrict__ tau_base,
    int s, int grow0)
{
    extern __shared__ float sm[];
    const int tid  = threadIdx.x;
    const int grp  = tid >> 8;
    const int gtid = tid & 255;
    const int w = gtid >> 5;        // 0..7
    const int l = gtid & 31;
    const int k0 = 16 * w;
    const int c0 = 4 * l;
    const bool owner = (gtid < 128);
    const int oc = gtid & 127;      // owner column
    const int ow = (gtid >> 5) & 3; // owner warp within 128

    float* gs   = sm + OFF_GRP + grp * GRP_STRIDE;
    float* sh   = gs;
    float* sx   = gs + 896;
    float* sp   = gs + 1792;
    float* sqp  = gs + 8960;
    float* sqs  = gs + 10752;
    float* sred = gs + 10976;
    const float* sWi  = sm + OFF_WI;
    const float* sV1  = sm + OFF_V1;
    const float* sV2  = sm + OFF_V2;
    const float* sbc  = sm + OFF_BC;
    const float* sv2b = sm + OFF_V2B;
    const float* sv1b = sm + OFF_V1B;

    const int barid = grp + 1;
    #define GBAR() asm volatile("bar.sync %0, 256;" :: "r"(barid) : "memory")

    // Wrec slice into registers: cols c0..c0+3, k in [k0, k0+16)  (64 regs)
    float wf[4][16];
    {
        const float* WrS = Wrec + s * 16384;
        #pragma unroll
        for (int i = 0; i < 4; i++)
            #pragma unroll
            for (int j = 0; j < 4; j++) {
                const float4 t = *(const float4*)&WrS[(c0 + i) * 128 + k0 + 4 * j];
                wf[i][4 * j + 0] = t.x;
                wf[i][4 * j + 1] = t.y;
                wf[i][4 * j + 2] = t.z;
                wf[i][4 * j + 3] = t.w;
            }
    }

    const float tb = tau_base[s * 128 + oc];
    float hj[G], xreg[G], inp[G], rtau[G];
    if (owner) {
        #pragma unroll
        for (int r = 0; r < G; r++) {
            hj[r] = 0.f;
            sh[r * 128 + oc] = 0.f;
            xreg[r] = g_xproj[(size_t)min(grow0 + r, BB - 1) * (TT * HH) + oc];
        }
    }
    GBAR();

    for (int t = 0; t < TT; t++) {
        if (owner) {
            #pragma unroll
            for (int r = 0; r < G; r++) sx[r * 128 + oc] = xreg[r];
        }
        GBAR();

        // ---- gate layer 1 partials: thread l = gate row, warp w = k-chunk ----
        {
            float qp[G];
            #pragma unroll
            for (int r = 0; r < G; r++) qp[r] = 0.f;
            #pragma unroll
            for (int kk = 0; kk < 16; kk += 4) {
                const float4 v4 = *(const float4*)&sV1[l * 132 + k0 + kk];
                #pragma unroll
                for (int r = 0; r < G; r++) {
                    const float4 x4 = *(const float4*)&sx[r * 128 + k0 + kk];
                    qp[r] = fmaf(x4.x, v4.x, qp[r]);
                    qp[r] = fmaf(x4.y, v4.y, qp[r]);
                    qp[r] = fmaf(x4.z, v4.z, qp[r]);
                    qp[r] = fmaf(x4.w, v4.w, qp[r]);
                }
            }
            #pragma unroll
            for (int r = 0; r < G; r++) sqp[r * 256 + w * 32 + l] = qp[r];
        }
        GBAR();
        if (gtid < 32) {
            #pragma unroll
            for (int r = 0; r < G; r++) {
                float q = sv1b[gtid];
                #pragma unroll
                for (int w2 = 0; w2 < 8; w2++)
                    q += sqp[r * 256 + w2 * 32 + gtid];
                sqs[r * 32 + gtid] = fmaxf(q, 0.f);
            }
        }
        GBAR();

        // ---- inp partials: x @ Wi^T, smem weights, 8-way k-split ----
        #pragma unroll
        for (int r = 0; r < G; r++) {
            float a0 = 0.f, a1 = 0.f, a2 = 0.f, a3 = 0.f;
            #pragma unroll
            for (int j = 0; j < 4; j++) {
                const float4 x4 = *(const float4*)&sx[r * 128 + k0 + 4 * j];
                const float4 w0 = *(const float4*)&sWi[(c0 + 0) * 132 + k0 + 4 * j];
                const float4 w1 = *(const float4*)&sWi[(c0 + 1) * 132 + k0 + 4 * j];
                const float4 w2 = *(const float4*)&sWi[(c0 + 2) * 132 + k0 + 4 * j];
                const float4 w3 = *(const float4*)&sWi[(c0 + 3) * 132 + k0 + 4 * j];
                a0 = fmaf(w0.x, x4.x, a0); a0 = fmaf(w0.y, x4.y, a0);
                a0 = fmaf(w0.z, x4.z, a0); a0 = fmaf(w0.w, x4.w, a0);
                a1 = fmaf(w1.x, x4.x, a1); a1 = fmaf(w1.y, x4.y, a1);
                a1 = fmaf(w1.z, x4.z, a1); a1 = fmaf(w1.w, x4.w, a1);
                a2 = fmaf(w2.x, x4.x, a2); a2 = fmaf(w2.y, x4.y, a2);
                a2 = fmaf(w2.z, x4.z, a2); a2 = fmaf(w2.w, x4.w, a2);
                a3 = fmaf(w3.x, x4.x, a3); a3 = fmaf(w3.y, x4.y, a3);
                a3 = fmaf(w3.z, x4.z, a3); a3 = fmaf(w3.w, x4.w, a3);
            }
            float4 v; v.x = a0; v.y = a1; v.z = a2; v.w = a3;
            *(float4*)&sp[(r * 8 + w) * 128 + c0] = v;
        }

        // ---- gate layer 2 -> rtau (owner threads; overlaps inp GEMM tail) ----
        if (owner) {
            float va[G];
            #pragma unroll
            for (int r = 0; r < G; r++) va[r] = sv2b[oc];
            #pragma unroll
            for (int ii = 0; ii < 32; ii += 4) {
                const float4 w4 = *(const float4*)&sV2[oc * 36 + ii];
                #pragma unroll
                for (int r = 0; r < G; r++) {
                    const float4 q4 = *(const float4*)&sqs[r * 32 + ii];
                    va[r] = fmaf(q4.x, w4.x, va[r]);
                    va[r] = fmaf(q4.y, w4.y, va[r]);
                    va[r] = fmaf(q4.z, w4.z, va[r]);
                    va[r] = fmaf(q4.w, w4.w, va[r]);
                }
            }
            #pragma unroll
            for (int r = 0; r < G; r++) {
                const float vol = __fdividef(1.f, 1.f + __expf(-va[r]));
                float ta = tb * (0.2f + 1.8f * (1.f - vol));
                ta = fminf(fmaxf(ta, 0.1f), 10.f);
                rtau[r] = __frcp_rn(ta);
            }
        }
        GBAR();

        if (owner) {
            #pragma unroll
            for (int r = 0; r < G; r++) {
                float v = sbc[oc];
                #pragma unroll
                for (int w2 = 0; w2 < 8; w2++)
                    v += sp[(r * 8 + w2) * 128 + oc];
                inp[r] = v;
            }
            // prefetch next timestep x (L2 hit; hidden behind inner steps)
            if (t + 1 < TT) {
                #pragma unroll
                for (int r = 0; r < G; r++)
                    xreg[r] = g_xproj[(size_t)min(grow0 + r, BB - 1) * (TT * HH)
                                      + (t + 1) * 128 + oc];
            }
        }
        GBAR();   // sp reads done before first inner overwrite

        // ---- inner ODE steps: register-weight GEMM, 3 barriers per step ----
        #pragma unroll 1
        for (int it = 0; it < NS; it++) {
            #pragma unroll
            for (int r = 0; r < G; r++) {
                float a0 = 0.f, a1 = 0.f, a2 = 0.f, a3 = 0.f;
                #pragma unroll
                for (int j = 0; j < 4; j++) {
                    const float4 x4 = *(const float4*)&sh[r * 128 + k0 + 4 * j];
                    a0 = fmaf(wf[0][4*j+0], x4.x, a0); a0 = fmaf(wf[0][4*j+1], x4.y, a0);
                    a0 = fmaf(wf[0][4*j+2], x4.z, a0); a0 = fmaf(wf[0][4*j+3], x4.w, a0);
                    a1 = fmaf(wf[1][4*j+0], x4.x, a1); a1 = fmaf(wf[1][4*j+1], x4.y, a1);
                    a1 = fmaf(wf[1][4*j+2], x4.z, a1); a1 = fmaf(wf[1][4*j+3], x4.w, a1);
                    a2 = fmaf(wf[2][4*j+0], x4.x, a2); a2 = fmaf(wf[2][4*j+1], x4.y, a2);
                    a2 = fmaf(wf[2][4*j+2], x4.z, a2); a2 = fmaf(wf[2][4*j+3], x4.w, a2);
                    a3 = fmaf(wf[3][4*j+0], x4.x, a3); a3 = fmaf(wf[3][4*j+1], x4.y, a3);
                    a3 = fmaf(wf[3][4*j+2], x4.z, a3); a3 = fmaf(wf[3][4*j+3], x4.w, a3);
                }
                float4 v; v.x = a0; v.y = a1; v.z = a2; v.w = a3;
                *(float4*)&sp[(r * 8 + w) * 128 + c0] = v;
            }
            GBAR();

            if (owner) {
                float d[G];
                #pragma unroll
                for (int r = 0; r < G; r++) {
                    float pre = inp[r];
                    #pragma unroll
                    for (int w2 = 0; w2 < 8; w2++)
                        pre += sp[(r * 8 + w2) * 128 + oc];
                    d[r] = (fast_tanh(pre) - hj[r]) * rtau[r];
                }
                #pragma unroll
                for (int r = 0; r < G; r++) {
                    float sq = d[r] * d[r];
                    sq += __shfl_xor_sync(0xffffffffu, sq, 16);
                    sq += __shfl_xor_sync(0xffffffffu, sq, 8);
                    sq += __shfl_xor_sync(0xffffffffu, sq, 4);
                    sq += __shfl_xor_sync(0xffffffffu, sq, 2);
                    sq += __shfl_xor_sync(0xffffffffu, sq, 1);
                    if (l == 0) sred[r * 4 + ow] = sq;
                }
                // keep d live across the barrier in hj-update below via regs
                GBAR();
                #pragma unroll
                for (int r = 0; r < G; r++) {
                    const float4 s4 = *(const float4*)&sred[r * 4];
                    const float mag = sqrtf(s4.x + s4.y + s4.z + s4.w);
                    const float coef = __fdividef(DTC, 1.f + 0.2f * mag);
                    hj[r] = fmaf(coef, d[r], hj[r]);
                    sh[r * 128 + oc] = hj[r];
                }
            } else {
                GBAR();
            }
            GBAR();   // sh visible (and sp free) before next pass
        }
    }

    if (owner) {
        #pragma unroll
        for (int r = 0; r < G; r++)
            g_hT[(s * BB + min(grow0 + r, BB - 1)) * HH + oc] = hj[r];
    }
    #undef GBAR
}

__global__ __launch_bounds__(512, 1) void liquid_kernel(
    const float* __restrict__ Wrec, const float* __restrict__ Win_w,
    const float* __restrict__ Win_b, const float* __restrict__ cbias,
    const float* __restrict__ tau_base,
    const float* __restrict__ v1w, const float* __restrict__ v1b,
    const float* __restrict__ v2w, const float* __restrict__ v2b)
{
    extern __shared__ float sm[];
    const int tid = threadIdx.x;
    const int b = blockIdx.x;

    int s, row0;
    if      (b < 21) { s = 0; row0 = b * 13; }
    else if (b < 53) { s = 1; row0 = (b - 21) * 8; }
    else if (b < 96) { s = 2; row0 = (b - 53) * 6; }
    else             { s = 3; row0 = (b - 96) * 5; }

    // stage Win ROW-major padded: sWi[col*132 + k]
    const float* Wi = Win_w + s * 16384;
    for (int idx = tid; idx < 16384; idx += 512) {
        const int j = idx >> 7, k = idx & 127;
        sm[OFF_WI + j * 132 + k] = Wi[idx];
    }
    for (int idx = tid; idx < 32 * 128; idx += 512) {
        int j = idx >> 7, k = idx & 127;
        sm[OFF_V1 + j * 132 + k] = v1w[s * 4096 + idx];
    }
    for (int idx = tid; idx < 128 * 32; idx += 512) {
        int j = idx >> 5, k = idx & 31;
        sm[OFF_V2 + j * 36 + k] = v2w[s * 4096 + idx];
    }
    if (tid < 128) {
        sm[OFF_BC  + tid] = Win_b[s * 128 + tid] + cbias[s * 128 + tid];
        sm[OFF_V2B + tid] = v2b[s * 128 + tid];
        if (tid < 32) sm[OFF_V1B + tid] = v1b[s * 32 + tid];
    }
    __syncthreads();

    const int grp = tid >> 8;
    if      (b < 21) { if (!grp) run_group<7, 3>(Wrec, tau_base, 0, row0);
                       else      run_group<6, 3>(Wrec, tau_base, 0, row0 + 7); }
    else if (b < 53) {           run_group<4, 5>(Wrec, tau_base, 1, row0 + grp * 4); }
    else if (b < 96) {           run_group<3, 7>(Wrec, tau_base, 2, row0 + grp * 3); }
    else             { if (!grp) run_group<3, 9>(Wrec, tau_base, 3, row0);
                       else      run_group<2, 9>(Wrec, tau_base, 3, row0 + 3); }
}

// ---------------------------------------------------------------------------
// K3: projection + concat + fusion MLP. One block per batch row.
// ---------------------------------------------------------------------------
__global__ __launch_bounds__(128) void head_kernel(
    const float* __restrict__ proj_w, const float* __restrict__ proj_b,
    const float* __restrict__ f1w, const float* __restrict__ f1b,
    const float* __restrict__ f2w, const float* __restrict__ f2b,
    const float* __restrict__ f3w, const float* __restrict__ f3b,
    float* __restrict__ out)
{
    __shared__ float fused[128];
    __shared__ float h1[128];
    __shared__ float h2[64];
    __shared__ float part[2];
    const int b = blockIdx.x;
    const int j = threadIdx.x;
    const int s = j >> 5, i = j & 31;

    {
        const float* h  = &g_hT[(s * BB + b) * HH];
        const float* pw = &proj_w[(s * 32 + i) * HH];
        float a = proj_b[s * 32 + i];
        #pragma unroll 8
        for (int k = 0; k < 128; k++) a = fmaf(h[k], pw[k], a);
        fused[j] = a;
    }
    __syncthreads();
    {
        float a = f1b[j];
        const float* wrow = &f1w[j * 128];
        #pragma unroll 8
        for (int k = 0; k < 128; k++) a = fmaf(fused[k], wrow[k], a);
        h1[j] = fmaxf(a, 0.f);
    }
    __syncthreads();
    if (j < 64) {
        float a = f2b[j];
        const float* wrow = &f2w[j * 128];
        #pragma unroll 8
        for (int k = 0; k < 128; k++) a = fmaf(h1[k], wrow[k], a);
        h2[j] = fmaxf(a, 0.f);
    }
    __syncthreads();
    if (j < 64) {
        float p = h2[j] * f3w[j];
        p += __shfl_xor_sync(0xffffffffu, p, 16);
        p += __shfl_xor_sync(0xffffffffu, p, 8);
        p += __shfl_xor_sync(0xffffffffu, p, 4);
        p += __shfl_xor_sync(0xffffffffu, p, 2);
        p += __shfl_xor_sync(0xffffffffu, p, 1);
        if ((j & 31) == 0) part[j >> 5] = p;
    }
    __syncthreads();
    if (j == 0) out[b] = part[0] + part[1] + f3b[0];
}

// ---------------------------------------------------------------------------
extern "C" void kernel_launch(void* const* d_in, const int* in_sizes, int n_in,
                              void* d_out, int out_size)
{
    const float* x        = (const float*)d_in[0];
    const float* Wp       = (const float*)d_in[1];
    const float* bp       = (const float*)d_in[2];
    const float* Wrec     = (const float*)d_in[3];
    const float* Win_w    = (const float*)d_in[4];
    const float* Win_b    = (const float*)d_in[5];
    const float* cbias    = (const float*)d_in[6];
    const float* tau_base = (const float*)d_in[7];
    const float* vg1_w    = (const float*)d_in[8];
    const float* vg1_b    = (const float*)d_in[9];
    const float* vg2_w    = (const float*)d_in[10];
    const float* vg2_b    = (const float*)d_in[11];
    const float* proj_w   = (const float*)d_in[12];
    const float* proj_b   = (const float*)d_in[13];
    const float* f1w      = (const float*)d_in[14];
    const float* f1b      = (const float*)d_in[15];
    const float* f2w      = (const float*)d_in[16];
    const float* f2b      = (const float*)d_in[17];
    const float* f3w      = (const float*)d_in[18];
    const float* f3b      = (const float*)d_in[19];
    float* out = (float*)d_out;

    cudaFuncSetAttribute(liquid_kernel,
                         cudaFuncAttributeMaxDynamicSharedMemorySize, SMEM_BYTES);

    xproj_kernel<<<(BB * TT) / 32, 128>>>(x, Wp, bp);
    liquid_kernel<<<148, 512, SMEM_BYTES>>>(Wrec, Win_w, Win_b, cbias, tau_base,
                                            vg1_w, vg1_b, vg2_w, vg2_b);
    head_kernel<<<BB, 128>>>(proj_w, proj_b, f1w, f1b, f2w, f2b, f3w, f3b, out);
}